// round 2
// baseline (speedup 1.0000x reference)
#include <cuda_runtime.h>

#define Hdim 128
#define HIDdim 512
#define PREP_BLOCKS 32
#define MAIN_BLOCKS 1184

// scratch (no allocations allowed)
__device__ float g_u_part[PREP_BLOCKS][Hdim];
__device__ float g_c_part[PREP_BLOCKS];
__device__ double g_sum;
__device__ unsigned long long g_maxkey;
__device__ unsigned g_count;

// ---------------------------------------------------------------------------
// K1 (prep): 32 blocks x 128 threads. Block b owns j in [16b, 16b+16).
//   phi1[j] = W1[j,:] . feat[prev,:] + b1[j]       (16 warp-dots per block)
//   u_part[b][h] = sum_{j in block} phi1[j]*W2[j,h]
//   c_part[b]    = sum_{j in block} phi1[j]*b2[j]
// Block 0 also resets the main-kernel accumulators.
// ---------------------------------------------------------------------------
__global__ void __launch_bounds__(128) k_prep(const float* __restrict__ feat,
                                              const float* __restrict__ W1,
                                              const float* __restrict__ b1,
                                              const float* __restrict__ W2,
                                              const float* __restrict__ b2,
                                              const int*   __restrict__ prev)
{
    __shared__ float sphi[16];

    const int lane = threadIdx.x & 31;
    const int warp = threadIdx.x >> 5;          // 0..3
    const int j0   = blockIdx.x * 16;
    const int p    = prev[0];

    const float4 x = ((const float4*)(feat + (size_t)p * Hdim))[lane];

#pragma unroll
    for (int jj = 0; jj < 4; jj++) {
        const int j = j0 + warp * 4 + jj;
        const float4 w = ((const float4*)(W1 + (size_t)j * Hdim))[lane];
        float d = fmaf(w.x, x.x, fmaf(w.y, x.y, fmaf(w.z, x.z, w.w * x.w)));
        d += __shfl_xor_sync(0xffffffffu, d, 16);
        d += __shfl_xor_sync(0xffffffffu, d, 8);
        d += __shfl_xor_sync(0xffffffffu, d, 4);
        d += __shfl_xor_sync(0xffffffffu, d, 2);
        d += __shfl_xor_sync(0xffffffffu, d, 1);
        if (lane == 0) sphi[warp * 4 + jj] = d + b1[j];
    }
    __syncthreads();

    const int h = threadIdx.x;                  // 0..127
    float acc = 0.0f;
#pragma unroll
    for (int jj = 0; jj < 16; jj++) {
        acc = fmaf(sphi[jj], W2[(size_t)(j0 + jj) * Hdim + h], acc);
    }
    g_u_part[blockIdx.x][h] = acc;

    if (threadIdx.x == 0) {
        float cp = 0.0f;
#pragma unroll
        for (int jj = 0; jj < 16; jj++) cp = fmaf(sphi[jj], b2[j0 + jj], cp);
        g_c_part[blockIdx.x] = cp;
        if (blockIdx.x == 0) { g_sum = 0.0; g_maxkey = 0ull; g_count = 0u; }
    }
}

// ---------------------------------------------------------------------------
// K2 (main, HBM-bound): one warp per node, skip row load when adj==0.
// attn = 10*tanh((u.x_n + c)/sqrt(512)); sum exp(attn) (masked -> exp(0)=1);
// track max attn + first index via packed 64-bit key. Last block finalizes.
// ---------------------------------------------------------------------------
__global__ void __launch_bounds__(256) k_main(const float* __restrict__ feat,
                                              const float* __restrict__ adj,
                                              float* __restrict__ out,
                                              int N, int out_size)
{
    __shared__ float              su[Hdim];
    __shared__ float              sc;
    __shared__ float              ssum[8];
    __shared__ unsigned long long skey[8];

    const int lane  = threadIdx.x & 31;
    const int wwarp = threadIdx.x >> 5;

    // Reconstruct u (coalesced: at each p, threads h=0..127 read consecutive)
    if (threadIdx.x < Hdim) {
        float a = 0.0f;
#pragma unroll
        for (int pb = 0; pb < PREP_BLOCKS; pb++) a += g_u_part[pb][threadIdx.x];
        su[threadIdx.x] = a;
    }
    if (threadIdx.x == Hdim) {
        float a = 0.0f;
#pragma unroll
        for (int pb = 0; pb < PREP_BLOCKS; pb++) a += g_c_part[pb];
        sc = a;
    }
    __syncthreads();

    const float4 u4 = ((const float4*)su)[lane];
    const float  c  = sc;

    const int gwarp = blockIdx.x * 8 + wwarp;
    const int nwarp = gridDim.x * 8;

    float lsum = 0.0f;
    unsigned long long lkey = 0ull;

    for (int n = gwarp; n < N; n += nwarp) {
        const float a = __ldg(adj + n);
        if (a != 0.0f) {
            const float4 x = ((const float4*)feat)[(size_t)n * 32 + lane];
            float d = fmaf(u4.x, x.x, fmaf(u4.y, x.y, fmaf(u4.z, x.z, u4.w * x.w)));
            d += __shfl_xor_sync(0xffffffffu, d, 16);
            d += __shfl_xor_sync(0xffffffffu, d, 8);
            d += __shfl_xor_sync(0xffffffffu, d, 4);
            d += __shfl_xor_sync(0xffffffffu, d, 2);
            d += __shfl_xor_sync(0xffffffffu, d, 1);
            if (lane == 0) {
                const float s    = (d + c) * 0.04419417382415922f; // 1/sqrt(512)
                const float attn = 10.0f * tanhf(s);
                lsum += expf(attn);
                if (attn != 0.0f) {
                    unsigned b   = __float_as_uint(attn);
                    unsigned enc = (b & 0x80000000u) ? ~b : (b | 0x80000000u);
                    unsigned long long key =
                        ((unsigned long long)enc << 32) |
                        (unsigned long long)(0xFFFFFFFFu - (unsigned)n);
                    if (key > lkey) lkey = key;
                }
            }
        } else if (lane == 0) {
            lsum += 1.0f;   // exp(0) for masked node
        }
    }

    if (lane == 0) { ssum[wwarp] = lsum; skey[wwarp] = lkey; }
    __syncthreads();

    if (threadIdx.x == 0) {
        float bs = 0.0f;
        unsigned long long bk = 0ull;
#pragma unroll
        for (int i = 0; i < 8; i++) {
            bs += ssum[i];
            if (skey[i] > bk) bk = skey[i];
        }
        atomicAdd(&g_sum, (double)bs);
        atomicMax(&g_maxkey, bk);
        __threadfence();
        const unsigned done = atomicAdd(&g_count, 1u);
        if (done == gridDim.x - 1u) {
            // last block: all other blocks' atomics are visible
            const double total = atomicAdd(&g_sum, 0.0);
            const unsigned long long k = atomicMax(&g_maxkey, 0ull);
            float pidx = 0.0f, pval = 0.0f;
            if (k != 0ull) {
                const unsigned enc = (unsigned)(k >> 32);
                const unsigned bb  = (enc & 0x80000000u) ? (enc ^ 0x80000000u) : ~enc;
                const float amax   = __uint_as_float(bb);
                const int   idx    = (int)(0xFFFFFFFFu - (unsigned)(k & 0xFFFFFFFFull));
                pidx = (float)idx;
                pval = (float)(exp((double)amax) / total);
            }
            out[0] = pidx;
            if (out_size > 1) out[1] = pval;
        }
    }
}

// ---------------------------------------------------------------------------
// inputs (metadata order): output[N,128], adj[N], W1[512,128], b1[512],
//                          W2[512,128], b2[512], prev_node (int scalar)
// ---------------------------------------------------------------------------
extern "C" void kernel_launch(void* const* d_in, const int* in_sizes, int n_in,
                              void* d_out, int out_size)
{
    const float* feat = (const float*)d_in[0];
    const float* adj  = (const float*)d_in[1];
    const float* W1   = (const float*)d_in[2];
    const float* b1   = (const float*)d_in[3];
    const float* W2   = (const float*)d_in[4];
    const float* b2   = (const float*)d_in[5];
    const int*   prev = (const int*)d_in[6];
    float* out = (float*)d_out;

    const int N = in_sizes[1];   // adj has N elements

    k_prep<<<PREP_BLOCKS, 128>>>(feat, W1, b1, W2, b2, prev);
    k_main<<<MAIN_BLOCKS, 256>>>(feat, adj, out, N, out_size);
}

// round 3
// speedup vs baseline: 1.3200x; 1.3200x over previous
#include <cuda_runtime.h>

#define Hdim 128
#define HIDdim 512
#define PREP_BLOCKS 32

// scratch (no allocations allowed)
__device__ float g_u_part[PREP_BLOCKS][Hdim];
__device__ float g_c_part[PREP_BLOCKS];
__device__ double g_sum;
__device__ unsigned long long g_maxkey;
__device__ unsigned g_count;

// ---------------------------------------------------------------------------
// K1 (prep): 32 blocks x 128 threads. Block b owns j in [16b, 16b+16).
//   phi1[j] = W1[j,:] . feat[prev,:] + b1[j]
//   u_part[b][h] = sum_j phi1[j]*W2[j,h],  c_part[b] = sum_j phi1[j]*b2[j]
// ---------------------------------------------------------------------------
__global__ void __launch_bounds__(128) k_prep(const float* __restrict__ feat,
                                              const float* __restrict__ W1,
                                              const float* __restrict__ b1,
                                              const float* __restrict__ W2,
                                              const float* __restrict__ b2,
                                              const int*   __restrict__ prev)
{
    __shared__ float sphi[16];

    const int lane = threadIdx.x & 31;
    const int warp = threadIdx.x >> 5;
    const int j0   = blockIdx.x * 16;
    const int p    = prev[0];

    const float4 x = ((const float4*)(feat + (size_t)p * Hdim))[lane];

#pragma unroll
    for (int jj = 0; jj < 4; jj++) {
        const int j = j0 + warp * 4 + jj;
        const float4 w = ((const float4*)(W1 + (size_t)j * Hdim))[lane];
        float d = fmaf(w.x, x.x, fmaf(w.y, x.y, fmaf(w.z, x.z, w.w * x.w)));
        d += __shfl_xor_sync(0xffffffffu, d, 16);
        d += __shfl_xor_sync(0xffffffffu, d, 8);
        d += __shfl_xor_sync(0xffffffffu, d, 4);
        d += __shfl_xor_sync(0xffffffffu, d, 2);
        d += __shfl_xor_sync(0xffffffffu, d, 1);
        if (lane == 0) sphi[warp * 4 + jj] = d + b1[j];
    }
    __syncthreads();

    const int h = threadIdx.x;
    float acc = 0.0f;
#pragma unroll
    for (int jj = 0; jj < 16; jj++) {
        acc = fmaf(sphi[jj], W2[(size_t)(j0 + jj) * Hdim + h], acc);
    }
    g_u_part[blockIdx.x][h] = acc;

    if (threadIdx.x == 0) {
        float cp = 0.0f;
#pragma unroll
        for (int jj = 0; jj < 16; jj++) cp = fmaf(sphi[jj], b2[j0 + jj], cp);
        g_c_part[blockIdx.x] = cp;
        if (blockIdx.x == 0) { g_sum = 0.0; g_maxkey = 0ull; g_count = 0u; }
    }
}

// ---------------------------------------------------------------------------
// K2 (main): one warp per contiguous 32-node chunk. Coalesced adj load +
// ballot; peel 4 active nodes at a time (MLP=4 row loads, 4 interleaved
// butterfly chains); lanes 0-3 run tanh/exp in parallel. Last block finalizes.
// ---------------------------------------------------------------------------
__global__ void __launch_bounds__(256) k_main(const float* __restrict__ feat,
                                              const float* __restrict__ adj,
                                              float* __restrict__ out,
                                              int N, int out_size)
{
    __shared__ float              su[Hdim];
    __shared__ float              sc;
    __shared__ float              ssum[8];
    __shared__ unsigned long long skey[8];

    const int lane  = threadIdx.x & 31;
    const int wwarp = threadIdx.x >> 5;

    // Reconstruct u (coalesced across partials)
    if (threadIdx.x < Hdim) {
        float a = 0.0f;
#pragma unroll
        for (int pb = 0; pb < PREP_BLOCKS; pb++) a += g_u_part[pb][threadIdx.x];
        su[threadIdx.x] = a;
    }
    if (threadIdx.x == Hdim) {
        float a = 0.0f;
#pragma unroll
        for (int pb = 0; pb < PREP_BLOCKS; pb++) a += g_c_part[pb];
        sc = a;
    }
    __syncthreads();

    const float4 u4 = ((const float4*)su)[lane];
    const float  c  = sc;
    const float4* __restrict__ fp = (const float4*)feat;

    float lsum = 0.0f;
    unsigned long long lkey = 0ull;

    const int base = (blockIdx.x * 8 + wwarp) * 32;
    if (base < N) {
        const int gn     = base + lane;
        const bool valid = gn < N;
        const float a    = valid ? __ldg(adj + gn) : 0.0f;
        unsigned mask    = __ballot_sync(0xffffffffu, valid && a != 0.0f);
        const int nvalid = (N - base >= 32) ? 32 : (N - base);

        if (lane == 0) lsum += (float)(nvalid - __popc(mask)); // exp(0) per masked

        while (mask) {
            const int i0 = __ffs(mask) - 1; mask &= mask - 1;
            int i1 = -1, i2 = -1, i3 = -1;
            if (mask) { i1 = __ffs(mask) - 1; mask &= mask - 1; }
            if (mask) { i2 = __ffs(mask) - 1; mask &= mask - 1; }
            if (mask) { i3 = __ffs(mask) - 1; mask &= mask - 1; }

            // independent row loads (MLP=4)
            const float4 x0 = fp[(size_t)(base + i0) * 32 + lane];
            float4 x1, x2, x3;
            if (i1 >= 0) x1 = fp[(size_t)(base + i1) * 32 + lane];
            if (i2 >= 0) x2 = fp[(size_t)(base + i2) * 32 + lane];
            if (i3 >= 0) x3 = fp[(size_t)(base + i3) * 32 + lane];

            float d0 = fmaf(u4.x, x0.x, fmaf(u4.y, x0.y, fmaf(u4.z, x0.z, u4.w * x0.w)));
            float d1 = (i1 >= 0) ? fmaf(u4.x, x1.x, fmaf(u4.y, x1.y, fmaf(u4.z, x1.z, u4.w * x1.w))) : 0.0f;
            float d2 = (i2 >= 0) ? fmaf(u4.x, x2.x, fmaf(u4.y, x2.y, fmaf(u4.z, x2.z, u4.w * x2.w))) : 0.0f;
            float d3 = (i3 >= 0) ? fmaf(u4.x, x3.x, fmaf(u4.y, x3.y, fmaf(u4.z, x3.z, u4.w * x3.w))) : 0.0f;

            // 4 interleaved butterfly chains
#pragma unroll
            for (int s = 16; s; s >>= 1) {
                d0 += __shfl_xor_sync(0xffffffffu, d0, s);
                d1 += __shfl_xor_sync(0xffffffffu, d1, s);
                d2 += __shfl_xor_sync(0xffffffffu, d2, s);
                d3 += __shfl_xor_sync(0xffffffffu, d3, s);
            }

            // lanes 0-3 each finish one node (parallel tanh/exp)
            const int   myi = (lane == 0) ? i0 : (lane == 1) ? i1
                            : (lane == 2) ? i2 : (lane == 3) ? i3 : -1;
            const float myd = (lane == 0) ? d0 : (lane == 1) ? d1
                            : (lane == 2) ? d2 : d3;
            if (myi >= 0 && lane < 4) {
                const float s    = (myd + c) * 0.04419417382415922f; // 1/sqrt(512)
                const float attn = 10.0f * tanhf(s);
                lsum += expf(attn);
                if (attn != 0.0f) {
                    const unsigned n   = (unsigned)(base + myi);
                    const unsigned b   = __float_as_uint(attn);
                    const unsigned enc = (b & 0x80000000u) ? ~b : (b | 0x80000000u);
                    const unsigned long long key =
                        ((unsigned long long)enc << 32) |
                        (unsigned long long)(0xFFFFFFFFu - n);
                    if (key > lkey) lkey = key;
                }
            }
        }
    }

    // warp-level reduce of lsum / lkey
#pragma unroll
    for (int s = 16; s; s >>= 1) {
        lsum += __shfl_xor_sync(0xffffffffu, lsum, s);
        const unsigned long long o = __shfl_xor_sync(0xffffffffu, lkey, s);
        if (o > lkey) lkey = o;
    }

    if (lane == 0) { ssum[wwarp] = lsum; skey[wwarp] = lkey; }
    __syncthreads();

    if (threadIdx.x == 0) {
        float bs = 0.0f;
        unsigned long long bk = 0ull;
#pragma unroll
        for (int i = 0; i < 8; i++) {
            bs += ssum[i];
            if (skey[i] > bk) bk = skey[i];
        }
        atomicAdd(&g_sum, (double)bs);
        atomicMax(&g_maxkey, bk);
        __threadfence();
        const unsigned done = atomicAdd(&g_count, 1u);
        if (done == gridDim.x - 1u) {
            const double total = atomicAdd(&g_sum, 0.0);
            const unsigned long long k = atomicMax(&g_maxkey, 0ull);
            float pidx = 0.0f, pval = 0.0f;
            if (k != 0ull) {
                const unsigned enc = (unsigned)(k >> 32);
                const unsigned bb  = (enc & 0x80000000u) ? (enc ^ 0x80000000u) : ~enc;
                const float amax   = __uint_as_float(bb);
                const int   idx    = (int)(0xFFFFFFFFu - (unsigned)(k & 0xFFFFFFFFull));
                pidx = (float)idx;
                pval = (float)(exp((double)amax) / total);
            }
            out[0] = pidx;
            if (out_size > 1) out[1] = pval;
        }
    }
}

// ---------------------------------------------------------------------------
// inputs (metadata order): output[N,128], adj[N], W1[512,128], b1[512],
//                          W2[512,128], b2[512], prev_node (int scalar)
// ---------------------------------------------------------------------------
extern "C" void kernel_launch(void* const* d_in, const int* in_sizes, int n_in,
                              void* d_out, int out_size)
{
    const float* feat = (const float*)d_in[0];
    const float* adj  = (const float*)d_in[1];
    const float* W1   = (const float*)d_in[2];
    const float* b1   = (const float*)d_in[3];
    const float* W2   = (const float*)d_in[4];
    const float* b2   = (const float*)d_in[5];
    const int*   prev = (const int*)d_in[6];
    float* out = (float*)d_out;

    const int N = in_sizes[1];               // adj has N elements
    const int warps  = (N + 31) / 32;        // one warp per 32-node chunk
    const int blocks = (warps + 7) / 8;

    k_prep<<<PREP_BLOCKS, 128>>>(feat, W1, b1, W2, b2, prev);
    k_main<<<blocks, 256>>>(feat, adj, out, N, out_size);
}